// round 17
// baseline (speedup 1.0000x reference)
#include <cuda_runtime.h>

// RankingLoss over all pairs, N=8192, single fused kernel (round-15 chassis).
// loss = sum_{i,j: dur_i<dur_j, ev_i==1} max(1-(p_i-p_j),0) / count (0 if count==0).
//
// Block = 256 threads owns 512 i-rows (=> ~256 compacted event rows, ALL warps
// work) and one 128-wide j-chunk => 1024 blocks (~7/SM for occupancy). Event
// rows block-locally compacted with an order-preserving ballot scan
// (deterministic). Unroll-8 inner loop, shuffle reductions. Last-arriving block
// reduces all partials in fixed order and writes the output.

#define NN   8192
#define TPB  256
#define IG   512                // i-rows per block (2 compaction rounds)
#define JC   128                // j-cols per block
#define GX   (NN / JC)          // 64
#define GYI  (NN / IG)          // 16
#define NBLK (GX * GYI)         // 1024
#define NW   (TPB / 32)         // 8 warps

__device__ float        g_s[NBLK];
__device__ unsigned int g_c[NBLK];
__device__ unsigned int g_tick = 0u;

__global__ void __launch_bounds__(TPB)
pair_kernel(const float* __restrict__ preds, const float* __restrict__ targets,
            float* __restrict__ out)
{
    __shared__ float4 tile4[JC / 2];     // {dur_2t, p_2t, dur_2t+1, p_2t+1}
    __shared__ float  sdur[IG];          // compacted event-row durations
    __shared__ float  scst[IG];          // compacted 1 - p_i
    __shared__ int    wcnt[2 * NW];
    __shared__ float        ws[NW];
    __shared__ unsigned int wcp[NW];
    __shared__ int    last_flag;

    const int tid  = threadIdx.x;
    const int wid  = tid >> 5;
    const int lane = tid & 31;
    const int i0   = blockIdx.y * IG + tid;
    const int i1   = i0 + TPB;
    const int j0   = blockIdx.x * JC;

    // --- load both i-rows, ballot per round ---
    const float2 t0 = ((const float2*)targets)[i0];
    const float2 t1 = ((const float2*)targets)[i1];
    const float  p0 = preds[i0];
    const float  p1 = preds[i1];
    const bool   f0 = (t0.y == 1.0f);
    const bool   f1 = (t1.y == 1.0f);
    const unsigned bm0 = __ballot_sync(0xffffffffu, f0);
    const unsigned bm1 = __ballot_sync(0xffffffffu, f1);
    if (lane == 0) {
        wcnt[wid]      = __popc(bm0);
        wcnt[NW + wid] = __popc(bm1);
    }

    // --- cooperative j-tile load (packed float4) ---
    for (int t = tid; t < JC / 2; t += TPB) {
        const int j = j0 + 2 * t;
        const float2 a = ((const float2*)targets)[j];
        const float2 b = ((const float2*)targets)[j + 1];
        tile4[t] = make_float4(a.x, preds[j], b.x, preds[j + 1]);
    }
    __syncthreads();

    // --- order-preserving prefix over 16 warp-counts ---
    int base0 = 0, base1 = 0, m = 0;
    #pragma unroll
    for (int w = 0; w < NW; ++w) {
        const int c = wcnt[w];
        if (w < wid) base0 += c;
        base1 += c;                      // round-1 bases start after all round-0
        m += c;
    }
    #pragma unroll
    for (int w = 0; w < NW; ++w) {
        const int c = wcnt[NW + w];
        if (w < wid) base1 += c;
        m += c;
    }
    if (f0) {
        const int pos = base0 + __popc(bm0 & ((1u << lane) - 1u));
        sdur[pos] = t0.x;
        scst[pos] = 1.0f - p0;
    }
    if (f1) {
        const int pos = base1 + __popc(bm1 & ((1u << lane) - 1u));
        sdur[pos] = t1.x;
        scst[pos] = 1.0f - p1;
    }
    __syncthreads();

    // --- main loop: all threads grid-stride over compacted rows ---
    float s0 = 0.0f, s1 = 0.0f, s2 = 0.0f, s3 = 0.0f;
    unsigned int c0 = 0u, c1 = 0u;
    for (int r = tid; r < m; r += TPB) {
        const float dur = sdur[r];
        const float c   = scst[r];
        #pragma unroll 8
        for (int t = 0; t < JC / 2; t += 2) {
            const float4 A = tile4[t];
            const float4 B = tile4[t + 1];
            if (dur < A.x) { s0 += fmaxf(c + A.y, 0.0f); c0++; }
            if (dur < A.z) { s1 += fmaxf(c + A.w, 0.0f); c1++; }
            if (dur < B.x) { s2 += fmaxf(c + B.y, 0.0f); c0++; }
            if (dur < B.z) { s3 += fmaxf(c + B.w, 0.0f); c1++; }
        }
    }

    // --- deterministic reduction: warp shuffle + tiny smem stage ---
    float        s   = (s0 + s1) + (s2 + s3);
    unsigned int cnt = c0 + c1;
    #pragma unroll
    for (int o = 16; o > 0; o >>= 1) {
        s   += __shfl_xor_sync(0xffffffffu, s, o);
        cnt += __shfl_xor_sync(0xffffffffu, cnt, o);
    }
    if (lane == 0) { ws[wid] = s; wcp[wid] = cnt; }
    __syncthreads();

    if (tid == 0) {
        float S = 0.0f; unsigned int C = 0u;
        #pragma unroll
        for (int w = 0; w < NW; ++w) { S += ws[w]; C += wcp[w]; }
        const int slot = blockIdx.y * GX + blockIdx.x;
        g_s[slot] = S;
        g_c[slot] = C;
        __threadfence();
        last_flag = (atomicAdd(&g_tick, 1u) == NBLK - 1u) ? 1 : 0;
    }
    __syncthreads();

    if (last_flag) {
        __threadfence();
        // 1024 partials -> 256 threads x 4, fixed order: deterministic.
        float        S = (g_s[tid] + g_s[tid + TPB]) +
                         (g_s[tid + 2 * TPB] + g_s[tid + 3 * TPB]);
        unsigned int C = (g_c[tid] + g_c[tid + TPB]) +
                         (g_c[tid + 2 * TPB] + g_c[tid + 3 * TPB]);
        #pragma unroll
        for (int o = 16; o > 0; o >>= 1) {
            S += __shfl_xor_sync(0xffffffffu, S, o);
            C += __shfl_xor_sync(0xffffffffu, C, o);
        }
        if (lane == 0) { ws[wid] = S; wcp[wid] = C; }
        __syncthreads();
        if (tid == 0) {
            float SS = 0.0f; unsigned int CC = 0u;
            #pragma unroll
            for (int w = 0; w < NW; ++w) { SS += ws[w]; CC += wcp[w]; }
            out[0] = (CC > 0u) ? (SS / (float)CC) : 0.0f;
            g_tick = 0u;                 // reset for next graph replay
        }
    }
}

extern "C" void kernel_launch(void* const* d_in, const int* in_sizes, int n_in,
                              void* d_out, int out_size)
{
    const float* preds   = (const float*)d_in[0];   // [8192]
    const float* targets = (const float*)d_in[1];   // [8192,2] {dur, ev}
    float* out = (float*)d_out;

    dim3 grid(GX, GYI);
    pair_kernel<<<grid, TPB>>>(preds, targets, out);
}